// round 7
// baseline (speedup 1.0000x reference)
#include <cuda_runtime.h>
#include <cuda_fp16.h>
#include <math.h>
#include <stdint.h>

#define B_   16
#define L_   1024
#define D_   512
#define E_   8
#define DFF_ 2048

// ---------------------------------------------------------------------------
// Scratch (static __device__ — no allocations allowed)
// ---------------------------------------------------------------------------
__device__ int    g_top1[B_];
__device__ __half g_h  [(size_t)B_ * L_ * DFF_];   // relu(x@W1+b1), fp16
__device__ __half g_xh [(size_t)B_ * L_ * D_];     // x rounded to fp16
__device__ __half g_w1t[(size_t)E_ * DFF_ * D_];   // W1^T per expert (N x K), fp16
__device__ __half g_w2t[(size_t)E_ * D_ * DFF_];   // W2^T per expert (N x K), fp16

__device__ __forceinline__ uint32_t smem_to_u32(const void* p) {
    uint32_t a;
    asm("{ .reg .u64 t; cvta.to.shared.u64 t, %1; cvt.u32.u64 %0, t; }" : "=r"(a) : "l"(p));
    return a;
}
__device__ __forceinline__ void cp_async16(uint32_t dst, const void* src) {
    asm volatile("cp.async.cg.shared.global [%0], [%1], 16;" :: "r"(dst), "l"(src) : "memory");
}
__device__ __forceinline__ void ldmatrix_x4(uint32_t& r0, uint32_t& r1, uint32_t& r2,
                                            uint32_t& r3, uint32_t addr) {
    asm volatile("ldmatrix.sync.aligned.m8n8.x4.shared.b16 {%0,%1,%2,%3}, [%4];"
                 : "=r"(r0), "=r"(r1), "=r"(r2), "=r"(r3) : "r"(addr));
}
__device__ __forceinline__ void mma_f16(float& c0, float& c1, float& c2, float& c3,
                                        uint32_t a0, uint32_t a1, uint32_t a2, uint32_t a3,
                                        uint32_t b0, uint32_t b1) {
    asm volatile("mma.sync.aligned.m16n8k16.row.col.f32.f16.f16.f32 "
                 "{%0,%1,%2,%3}, {%4,%5,%6,%7}, {%8,%9}, {%0,%1,%2,%3};"
                 : "+f"(c0), "+f"(c1), "+f"(c2), "+f"(c3)
                 : "r"(a0), "r"(a1), "r"(a2), "r"(a3), "r"(b0), "r"(b1));
}

// ---------------------------------------------------------------------------
// Fused prep: router + x->fp16 round + W1/W2 transpose->fp16, one kernel.
// ---------------------------------------------------------------------------
#define PREP_W1_BLKS 8192
#define PREP_W2_BLKS 8192
#define PREP_X_BLKS  2048
#define PREP_TOTAL   (PREP_W1_BLKS + PREP_W2_BLKS + PREP_X_BLKS + 1)

__global__ void __launch_bounds__(256)
prep_fused(const float* __restrict__ x,
           const float* __restrict__ W1, const float* __restrict__ W2,
           const int* __restrict__ view_ids, const int* __restrict__ visit_ids,
           const float* __restrict__ router_view, const float* __restrict__ router_visit,
           float* loss_out,
           __half* __restrict__ xh, __half* __restrict__ w1t, __half* __restrict__ w2t) {
    const int bid = blockIdx.x;
    const int tid = threadIdx.x;

    if (bid < PREP_W1_BLKS + PREP_W2_BLKS) {
        __shared__ float t[32][33];
        const float* in;
        __half* out;
        int R, C, r0, c0;
        if (bid < PREP_W1_BLKS) {
            const int e = bid >> 10, tt = bid & 1023;
            R = D_; C = DFF_;
            r0 = (tt >> 6) * 32; c0 = (tt & 63) * 32;
            in  = W1  + (size_t)e * R * C;
            out = w1t + (size_t)e * C * R;
        } else {
            const int bb = bid - PREP_W1_BLKS;
            const int e = bb >> 10, tt = bb & 1023;
            R = DFF_; C = D_;
            r0 = (tt >> 4) * 32; c0 = (tt & 15) * 32;
            in  = W2  + (size_t)e * R * C;
            out = w2t + (size_t)e * C * R;
        }
        const int tx = tid & 31, ty = tid >> 5;
#pragma unroll
        for (int i = ty; i < 32; i += 8)
            t[i][tx] = in[(size_t)(r0 + i) * C + c0 + tx];
        __syncthreads();
#pragma unroll
        for (int i = ty; i < 32; i += 8)
            out[(size_t)(c0 + i) * R + r0 + tx] = __float2half_rn(t[tx][i]);
        return;
    }

    if (bid < PREP_W1_BLKS + PREP_W2_BLKS + PREP_X_BLKS) {
        const int xb = bid - (PREP_W1_BLKS + PREP_W2_BLKS);
        const int n4 = (B_ * L_ * D_) / 4;       // 2,097,152 float4
        const float4* in = (const float4*)x;
        uint2* out = (uint2*)xh;
        for (int i = xb * 256 + tid; i < n4; i += PREP_X_BLKS * 256) {
            const float4 v = in[i];
            const __half2 h01 = __floats2half2_rn(v.x, v.y);
            const __half2 h23 = __floats2half2_rn(v.z, v.w);
            uint2 o;
            o.x = *(const uint32_t*)&h01;
            o.y = *(const uint32_t*)&h23;
            out[i] = o;
        }
        return;
    }

    // Router + balance loss (1 thread)
    if (tid == 0) {
        float load[E_];
#pragma unroll
        for (int e = 0; e < E_; e++) load[e] = 0.0f;
        for (int b = 0; b < B_; b++) {
            const int vi = view_ids[b];
            const int vs = visit_ids[b];
            float lg[E_];
            float m = -1e30f; int am = 0;
#pragma unroll
            for (int e = 0; e < E_; e++) {
                lg[e] = router_view[vi * E_ + e] + router_visit[vs * E_ + e];
                if (lg[e] > m) { m = lg[e]; am = e; }
            }
            g_top1[b] = am;
            float s = 0.0f;
#pragma unroll
            for (int e = 0; e < E_; e++) { lg[e] = expf(lg[e] - m); s += lg[e]; }
            const float inv = 1.0f / s;
#pragma unroll
            for (int e = 0; e < E_; e++) load[e] += lg[e] * inv;
        }
        float loss = 0.0f;
#pragma unroll
        for (int e = 0; e < E_; e++) {
            const float ld = load[e] * (1.0f / (float)B_);
            loss -= ld * logf(ld);
        }
        if (loss_out) *loss_out = loss;
    }
}

// ---------------------------------------------------------------------------
// FP16 tensor-core GEMM via mma.sync m16n8k16 (fp32 accumulate):
//   Y[b] = act( A[b] (MxK row-major fp16) @ B[e_b]^T (NxK K-major fp16) + bias )
// CTA tile 128x128x64, 8 warps in 2x4, warp tile 64x32. 3-stage cp.async,
// 2 CTAs/SM (110.6KB smem each), ONE __syncthreads per ktile.
// ---------------------------------------------------------------------------
#define STAGES 3
#define A_TILE_BYTES 18432               // 128 rows * 144B
#define STAGE_BYTES  36864               // A + B (128 rows each)

template <bool OUT_HALF>
__global__ void __launch_bounds__(256, 2)
gemm_f16_mma(const __half* __restrict__ Aall, const __half* __restrict__ Ball,
             const float* __restrict__ biasAll, void* __restrict__ Yall,
             int M, int N, int K) {
    extern __shared__ __align__(128) char smem[];
    const uint32_t smem_base = smem_to_u32(smem);

    const int tid  = threadIdx.x;
    const int wid  = tid >> 5;
    const int lane = tid & 31;
    const int mbase = (wid & 1) * 64;    // 2 warp rows
    const int nbase = (wid >> 1) * 32;   // 4 warp cols

    const int b = blockIdx.z;
    const int e = g_top1[b];
    const int block_row = blockIdx.y * 128;
    const int block_col = blockIdx.x * 128;

    const __half* Aptr = Aall + (size_t)b * M * K + (size_t)block_row * K;
    const __half* Bptr = Ball + (size_t)e * N * K + (size_t)block_col * K;
    const float* bias = biasAll + (size_t)e * N + block_col;

    const int T = K >> 6;                // BK = 64

    // -------- cp.async loader: A 128x64h + B 128x64h, 2048 16B chunks -------
    auto load_tile = [&](int t, int stage) {
        const __half* Ag = Aptr + t * 64;
        const __half* Bg = Bptr + t * 64;
        const uint32_t sa = smem_base + stage * STAGE_BYTES;
        const uint32_t sb = sa + A_TILE_BYTES;
#pragma unroll
        for (int i = 0; i < 4; i++) {
            const int idx = tid + i * 256;
            const int r = idx >> 3, q = idx & 7;
            cp_async16(sa + r * 144 + q * 16, Ag + (size_t)r * K + q * 8);
            cp_async16(sb + r * 144 + q * 16, Bg + (size_t)r * K + q * 8);
        }
        asm volatile("cp.async.commit_group;" ::: "memory");
    };

    float acc[4][4][4];
#pragma unroll
    for (int i = 0; i < 4; i++)
#pragma unroll
        for (int j = 0; j < 4; j++)
#pragma unroll
            for (int r = 0; r < 4; r++) acc[i][j][r] = 0.0f;

#pragma unroll
    for (int s = 0; s < STAGES - 1; s++)
        if (s < T) load_tile(s, s);

    // ldmatrix lane addressing (byte offsets; k+8 halves = +16B)
    const int a_row = mbase + (lane & 15);
    const int a_coff = ((lane >> 4) & 1) * 16;
    const int b_row_off = (lane & 7) + ((lane >> 4) & 1) * 8;
    const int b_coff = ((lane >> 3) & 1) * 16;

    for (int t = 0; t < T; t++) {
        // Stage t must be resident: allow 1 pending group unless this is the last.
        if (t < T - 1) asm volatile("cp.async.wait_group 1;" ::: "memory");
        else           asm volatile("cp.async.wait_group 0;" ::: "memory");
        __syncthreads();   // single barrier per ktile

        // Issue next load (overwrites stage consumed in iter t-1; all reads of
        // it completed before the barrier above — ldmatrix results land in
        // registers before the issuing warp reaches the barrier).
        if (t + STAGES - 1 < T) load_tile(t + STAGES - 1, (t + STAGES - 1) % STAGES);

        const uint32_t sa = smem_base + (t % STAGES) * STAGE_BYTES;
        const uint32_t sb = sa + A_TILE_BYTES;

#pragma unroll
        for (int ks = 0; ks < 4; ks++) {
            const int kc = ks * 32;                      // 16 halves per kstep
            uint32_t af[4][4];
#pragma unroll
            for (int mt = 0; mt < 4; mt++) {
                const uint32_t addr = sa + (a_row + mt * 16) * 144 + kc + a_coff;
                ldmatrix_x4(af[mt][0], af[mt][1], af[mt][2], af[mt][3], addr);
            }
            uint32_t bf[4][2];
#pragma unroll
            for (int p = 0; p < 2; p++) {
                const uint32_t addr = sb + (nbase + p * 16 + b_row_off) * 144 + kc + b_coff;
                ldmatrix_x4(bf[2 * p][0], bf[2 * p][1], bf[2 * p + 1][0], bf[2 * p + 1][1], addr);
            }
#pragma unroll
            for (int mt = 0; mt < 4; mt++)
#pragma unroll
                for (int nt = 0; nt < 4; nt++)
                    mma_f16(acc[mt][nt][0], acc[mt][nt][1], acc[mt][nt][2], acc[mt][nt][3],
                            af[mt][0], af[mt][1], af[mt][2], af[mt][3],
                            bf[nt][0], bf[nt][1]);
        }
    }

    // -------- Epilogue --------
    const int gid = lane >> 2;          // 0..7
    const int tig = lane & 3;           // 0..3
#pragma unroll
    for (int nt = 0; nt < 4; nt++) {
        const int coll = nbase + nt * 8 + 2 * tig;
        const float2 bv = *(const float2*)&bias[coll];
        const int col = block_col + coll;
#pragma unroll
        for (int mt = 0; mt < 4; mt++) {
            const int row0 = block_row + mbase + mt * 16 + gid;
            float2 v0, v1;
            v0.x = acc[mt][nt][0] + bv.x;
            v0.y = acc[mt][nt][1] + bv.y;
            v1.x = acc[mt][nt][2] + bv.x;
            v1.y = acc[mt][nt][3] + bv.y;
            if (OUT_HALF) {
                __half* Y = (__half*)Yall + (size_t)b * M * N;
                const __half2 h0 = __floats2half2_rn(fmaxf(v0.x, 0.0f), fmaxf(v0.y, 0.0f));
                const __half2 h1 = __floats2half2_rn(fmaxf(v1.x, 0.0f), fmaxf(v1.y, 0.0f));
                *(__half2*)&Y[(size_t)row0 * N + col] = h0;
                *(__half2*)&Y[(size_t)(row0 + 8) * N + col] = h1;
            } else {
                float* Y = (float*)Yall + (size_t)b * M * N;
                *(float2*)&Y[(size_t)row0 * N + col] = v0;
                *(float2*)&Y[(size_t)(row0 + 8) * N + col] = v1;
            }
        }
    }
}

// ---------------------------------------------------------------------------
// Launch
// ---------------------------------------------------------------------------
extern "C" void kernel_launch(void* const* d_in, const int* in_sizes, int n_in,
                              void* d_out, int out_size) {
    const float* x            = (const float*)d_in[0];
    const int*   view_ids     = (const int*)d_in[1];
    const int*   visit_ids    = (const int*)d_in[2];
    const float* router_view  = (const float*)d_in[3];
    const float* router_visit = (const float*)d_in[4];
    const float* W1           = (const float*)d_in[5];
    const float* b1           = (const float*)d_in[6];
    const float* W2           = (const float*)d_in[7];
    const float* b2           = (const float*)d_in[8];
    float* out = (float*)d_out;

    const size_t out_elems = (size_t)B_ * L_ * D_;
    float* loss_ptr = ((size_t)out_size > out_elems) ? (out + out_elems) : nullptr;

    __half *h_ptr, *xh_ptr, *w1t_ptr, *w2t_ptr;
    cudaGetSymbolAddress((void**)&h_ptr,   g_h);
    cudaGetSymbolAddress((void**)&xh_ptr,  g_xh);
    cudaGetSymbolAddress((void**)&w1t_ptr, g_w1t);
    cudaGetSymbolAddress((void**)&w2t_ptr, g_w2t);

    const int SMEM_BYTES = STAGES * STAGE_BYTES;   // 110592 -> 2 CTAs/SM
    cudaFuncSetAttribute((const void*)gemm_f16_mma<true>,
                         cudaFuncAttributeMaxDynamicSharedMemorySize, SMEM_BYTES);
    cudaFuncSetAttribute((const void*)gemm_f16_mma<false>,
                         cudaFuncAttributeMaxDynamicSharedMemorySize, SMEM_BYTES);

    // Fused prep: router + x fp16 round + W1/W2 transpose (all parallel)
    prep_fused<<<PREP_TOTAL, 256>>>(x, W1, W2, view_ids, visit_ids,
                                    router_view, router_visit, loss_ptr,
                                    xh_ptr, w1t_ptr, w2t_ptr);

    // GEMM1: h = fp16(relu(x @ W1 + b1))   M=1024, N=2048, K=512
    gemm_f16_mma<true><<<dim3(DFF_ / 128, L_ / 128, B_), 256, SMEM_BYTES>>>(
        xh_ptr, w1t_ptr, b1, h_ptr, L_, DFF_, D_);

    // GEMM2: out = h @ W2 + b2             M=1024, N=512, K=2048
    gemm_f16_mma<false><<<dim3(D_ / 128, L_ / 128, B_), 256, SMEM_BYTES>>>(
        h_ptr, w2t_ptr, b2, out, L_, D_, DFF_);
}

// round 8
// speedup vs baseline: 1.0029x; 1.0029x over previous
#include <cuda_runtime.h>
#include <cuda_fp16.h>
#include <math.h>
#include <stdint.h>

#define B_   16
#define L_   1024
#define D_   512
#define E_   8
#define DFF_ 2048

// ---------------------------------------------------------------------------
// Scratch (static __device__ — no allocations allowed)
// ---------------------------------------------------------------------------
__device__ int    g_top1[B_];
__device__ __half g_h  [(size_t)B_ * L_ * DFF_];   // relu(x@W1+b1), fp16
__device__ __half g_xh [(size_t)B_ * L_ * D_];     // x rounded to fp16
__device__ __half g_w1t[(size_t)E_ * DFF_ * D_];   // W1^T per expert (N x K), fp16
__device__ __half g_w2t[(size_t)E_ * D_ * DFF_];   // W2^T per expert (N x K), fp16

__device__ __forceinline__ uint32_t smem_to_u32(const void* p) {
    uint32_t a;
    asm("{ .reg .u64 t; cvta.to.shared.u64 t, %1; cvt.u32.u64 %0, t; }" : "=r"(a) : "l"(p));
    return a;
}
__device__ __forceinline__ void cp_async16(uint32_t dst, const void* src) {
    asm volatile("cp.async.cg.shared.global [%0], [%1], 16;" :: "r"(dst), "l"(src) : "memory");
}
__device__ __forceinline__ void ldmatrix_x4(uint32_t& r0, uint32_t& r1, uint32_t& r2,
                                            uint32_t& r3, uint32_t addr) {
    asm volatile("ldmatrix.sync.aligned.m8n8.x4.shared.b16 {%0,%1,%2,%3}, [%4];"
                 : "=r"(r0), "=r"(r1), "=r"(r2), "=r"(r3) : "r"(addr));
}
__device__ __forceinline__ void mma_f16(float& c0, float& c1, float& c2, float& c3,
                                        uint32_t a0, uint32_t a1, uint32_t a2, uint32_t a3,
                                        uint32_t b0, uint32_t b1) {
    asm volatile("mma.sync.aligned.m16n8k16.row.col.f32.f16.f16.f32 "
                 "{%0,%1,%2,%3}, {%4,%5,%6,%7}, {%8,%9}, {%0,%1,%2,%3};"
                 : "+f"(c0), "+f"(c1), "+f"(c2), "+f"(c3)
                 : "r"(a0), "r"(a1), "r"(a2), "r"(a3), "r"(b0), "r"(b1));
}

// ---------------------------------------------------------------------------
// Fused prep: router + x->fp16 round + W1/W2 transpose->fp16, one kernel.
// ---------------------------------------------------------------------------
#define PREP_W1_BLKS 8192
#define PREP_W2_BLKS 8192
#define PREP_X_BLKS  2048
#define PREP_TOTAL   (PREP_W1_BLKS + PREP_W2_BLKS + PREP_X_BLKS + 1)

__global__ void __launch_bounds__(256)
prep_fused(const float* __restrict__ x,
           const float* __restrict__ W1, const float* __restrict__ W2,
           const int* __restrict__ view_ids, const int* __restrict__ visit_ids,
           const float* __restrict__ router_view, const float* __restrict__ router_visit,
           float* loss_out,
           __half* __restrict__ xh, __half* __restrict__ w1t, __half* __restrict__ w2t) {
    const int bid = blockIdx.x;
    const int tid = threadIdx.x;

    if (bid < PREP_W1_BLKS + PREP_W2_BLKS) {
        __shared__ float t[32][33];
        const float* in;
        __half* out;
        int R, C, r0, c0;
        if (bid < PREP_W1_BLKS) {
            const int e = bid >> 10, tt = bid & 1023;
            R = D_; C = DFF_;
            r0 = (tt >> 6) * 32; c0 = (tt & 63) * 32;
            in  = W1  + (size_t)e * R * C;
            out = w1t + (size_t)e * C * R;
        } else {
            const int bb = bid - PREP_W1_BLKS;
            const int e = bb >> 10, tt = bb & 1023;
            R = DFF_; C = D_;
            r0 = (tt >> 4) * 32; c0 = (tt & 15) * 32;
            in  = W2  + (size_t)e * R * C;
            out = w2t + (size_t)e * C * R;
        }
        const int tx = tid & 31, ty = tid >> 5;
#pragma unroll
        for (int i = ty; i < 32; i += 8)
            t[i][tx] = in[(size_t)(r0 + i) * C + c0 + tx];
        __syncthreads();
#pragma unroll
        for (int i = ty; i < 32; i += 8)
            out[(size_t)(c0 + i) * R + r0 + tx] = __float2half_rn(t[tx][i]);
        return;
    }

    if (bid < PREP_W1_BLKS + PREP_W2_BLKS + PREP_X_BLKS) {
        const int xb = bid - (PREP_W1_BLKS + PREP_W2_BLKS);
        const int n4 = (B_ * L_ * D_) / 4;       // 2,097,152 float4
        const float4* in = (const float4*)x;
        uint2* out = (uint2*)xh;
        for (int i = xb * 256 + tid; i < n4; i += PREP_X_BLKS * 256) {
            const float4 v = in[i];
            const __half2 h01 = __floats2half2_rn(v.x, v.y);
            const __half2 h23 = __floats2half2_rn(v.z, v.w);
            uint2 o;
            o.x = *(const uint32_t*)&h01;
            o.y = *(const uint32_t*)&h23;
            out[i] = o;
        }
        return;
    }

    // Router + balance loss (1 thread)
    if (tid == 0) {
        float load[E_];
#pragma unroll
        for (int e = 0; e < E_; e++) load[e] = 0.0f;
        for (int b = 0; b < B_; b++) {
            const int vi = view_ids[b];
            const int vs = visit_ids[b];
            float lg[E_];
            float m = -1e30f; int am = 0;
#pragma unroll
            for (int e = 0; e < E_; e++) {
                lg[e] = router_view[vi * E_ + e] + router_visit[vs * E_ + e];
                if (lg[e] > m) { m = lg[e]; am = e; }
            }
            g_top1[b] = am;
            float s = 0.0f;
#pragma unroll
            for (int e = 0; e < E_; e++) { lg[e] = expf(lg[e] - m); s += lg[e]; }
            const float inv = 1.0f / s;
#pragma unroll
            for (int e = 0; e < E_; e++) load[e] += lg[e] * inv;
        }
        float loss = 0.0f;
#pragma unroll
        for (int e = 0; e < E_; e++) {
            const float ld = load[e] * (1.0f / (float)B_);
            loss -= ld * logf(ld);
        }
        if (loss_out) *loss_out = loss;
    }
}

// ---------------------------------------------------------------------------
// FP16 tensor-core GEMM via mma.sync m16n8k16 (fp32 accumulate):
//   Y[b] = act( A[b] (MxK row-major fp16) @ B[e_b]^T (NxK K-major fp16) + bias )
// CTA tile 128x128x64, 8 warps in 2x4, warp tile 64x32. 3-stage cp.async,
// 2 CTAs/SM (110.6KB smem each), ONE __syncthreads per ktile.
// ---------------------------------------------------------------------------
#define STAGES 3
#define A_TILE_BYTES 18432               // 128 rows * 144B
#define STAGE_BYTES  36864               // A + B (128 rows each)

template <bool OUT_HALF>
__global__ void __launch_bounds__(256, 2)
gemm_f16_mma(const __half* __restrict__ Aall, const __half* __restrict__ Ball,
             const float* __restrict__ biasAll, void* __restrict__ Yall,
             int M, int N, int K) {
    extern __shared__ __align__(128) char smem[];
    const uint32_t smem_base = smem_to_u32(smem);

    const int tid  = threadIdx.x;
    const int wid  = tid >> 5;
    const int lane = tid & 31;
    const int mbase = (wid & 1) * 64;    // 2 warp rows
    const int nbase = (wid >> 1) * 32;   // 4 warp cols

    const int b = blockIdx.z;
    const int e = g_top1[b];
    const int block_row = blockIdx.y * 128;
    const int block_col = blockIdx.x * 128;

    const __half* Aptr = Aall + (size_t)b * M * K + (size_t)block_row * K;
    const __half* Bptr = Ball + (size_t)e * N * K + (size_t)block_col * K;
    const float* bias = biasAll + (size_t)e * N + block_col;

    const int T = K >> 6;                // BK = 64

    // -------- cp.async loader: A 128x64h + B 128x64h, 2048 16B chunks -------
    auto load_tile = [&](int t, int stage) {
        const __half* Ag = Aptr + t * 64;
        const __half* Bg = Bptr + t * 64;
        const uint32_t sa = smem_base + stage * STAGE_BYTES;
        const uint32_t sb = sa + A_TILE_BYTES;
#pragma unroll
        for (int i = 0; i < 4; i++) {
            const int idx = tid + i * 256;
            const int r = idx >> 3, q = idx & 7;
            cp_async16(sa + r * 144 + q * 16, Ag + (size_t)r * K + q * 8);
            cp_async16(sb + r * 144 + q * 16, Bg + (size_t)r * K + q * 8);
        }
        asm volatile("cp.async.commit_group;" ::: "memory");
    };

    float acc[4][4][4];
#pragma unroll
    for (int i = 0; i < 4; i++)
#pragma unroll
        for (int j = 0; j < 4; j++)
#pragma unroll
            for (int r = 0; r < 4; r++) acc[i][j][r] = 0.0f;

#pragma unroll
    for (int s = 0; s < STAGES - 1; s++)
        if (s < T) load_tile(s, s);

    // ldmatrix lane addressing (byte offsets; k+8 halves = +16B)
    const int a_row = mbase + (lane & 15);
    const int a_coff = ((lane >> 4) & 1) * 16;
    const int b_row_off = (lane & 7) + ((lane >> 4) & 1) * 8;
    const int b_coff = ((lane >> 3) & 1) * 16;

    for (int t = 0; t < T; t++) {
        // Stage t must be resident: allow 1 pending group unless this is the last.
        if (t < T - 1) asm volatile("cp.async.wait_group 1;" ::: "memory");
        else           asm volatile("cp.async.wait_group 0;" ::: "memory");
        __syncthreads();   // single barrier per ktile

        // Issue next load (overwrites stage consumed in iter t-1; all reads of
        // it completed before the barrier above — ldmatrix results land in
        // registers before the issuing warp reaches the barrier).
        if (t + STAGES - 1 < T) load_tile(t + STAGES - 1, (t + STAGES - 1) % STAGES);

        const uint32_t sa = smem_base + (t % STAGES) * STAGE_BYTES;
        const uint32_t sb = sa + A_TILE_BYTES;

#pragma unroll
        for (int ks = 0; ks < 4; ks++) {
            const int kc = ks * 32;                      // 16 halves per kstep
            uint32_t af[4][4];
#pragma unroll
            for (int mt = 0; mt < 4; mt++) {
                const uint32_t addr = sa + (a_row + mt * 16) * 144 + kc + a_coff;
                ldmatrix_x4(af[mt][0], af[mt][1], af[mt][2], af[mt][3], addr);
            }
            uint32_t bf[4][2];
#pragma unroll
            for (int p = 0; p < 2; p++) {
                const uint32_t addr = sb + (nbase + p * 16 + b_row_off) * 144 + kc + b_coff;
                ldmatrix_x4(bf[2 * p][0], bf[2 * p][1], bf[2 * p + 1][0], bf[2 * p + 1][1], addr);
            }
#pragma unroll
            for (int mt = 0; mt < 4; mt++)
#pragma unroll
                for (int nt = 0; nt < 4; nt++)
                    mma_f16(acc[mt][nt][0], acc[mt][nt][1], acc[mt][nt][2], acc[mt][nt][3],
                            af[mt][0], af[mt][1], af[mt][2], af[mt][3],
                            bf[nt][0], bf[nt][1]);
        }
    }

    // -------- Epilogue --------
    const int gid = lane >> 2;          // 0..7
    const int tig = lane & 3;           // 0..3
#pragma unroll
    for (int nt = 0; nt < 4; nt++) {
        const int coll = nbase + nt * 8 + 2 * tig;
        const float2 bv = *(const float2*)&bias[coll];
        const int col = block_col + coll;
#pragma unroll
        for (int mt = 0; mt < 4; mt++) {
            const int row0 = block_row + mbase + mt * 16 + gid;
            float2 v0, v1;
            v0.x = acc[mt][nt][0] + bv.x;
            v0.y = acc[mt][nt][1] + bv.y;
            v1.x = acc[mt][nt][2] + bv.x;
            v1.y = acc[mt][nt][3] + bv.y;
            if (OUT_HALF) {
                __half* Y = (__half*)Yall + (size_t)b * M * N;
                const __half2 h0 = __floats2half2_rn(fmaxf(v0.x, 0.0f), fmaxf(v0.y, 0.0f));
                const __half2 h1 = __floats2half2_rn(fmaxf(v1.x, 0.0f), fmaxf(v1.y, 0.0f));
                *(__half2*)&Y[(size_t)row0 * N + col] = h0;
                *(__half2*)&Y[(size_t)(row0 + 8) * N + col] = h1;
            } else {
                float* Y = (float*)Yall + (size_t)b * M * N;
                *(float2*)&Y[(size_t)row0 * N + col] = v0;
                *(float2*)&Y[(size_t)(row0 + 8) * N + col] = v1;
            }
        }
    }
}

// ---------------------------------------------------------------------------
// Launch
// ---------------------------------------------------------------------------
extern "C" void kernel_launch(void* const* d_in, const int* in_sizes, int n_in,
                              void* d_out, int out_size) {
    const float* x            = (const float*)d_in[0];
    const int*   view_ids     = (const int*)d_in[1];
    const int*   visit_ids    = (const int*)d_in[2];
    const float* router_view  = (const float*)d_in[3];
    const float* router_visit = (const float*)d_in[4];
    const float* W1           = (const float*)d_in[5];
    const float* b1           = (const float*)d_in[6];
    const float* W2           = (const float*)d_in[7];
    const float* b2           = (const float*)d_in[8];
    float* out = (float*)d_out;

    const size_t out_elems = (size_t)B_ * L_ * D_;
    float* loss_ptr = ((size_t)out_size > out_elems) ? (out + out_elems) : nullptr;

    __half *h_ptr, *xh_ptr, *w1t_ptr, *w2t_ptr;
    cudaGetSymbolAddress((void**)&h_ptr,   g_h);
    cudaGetSymbolAddress((void**)&xh_ptr,  g_xh);
    cudaGetSymbolAddress((void**)&w1t_ptr, g_w1t);
    cudaGetSymbolAddress((void**)&w2t_ptr, g_w2t);

    const int SMEM_BYTES = STAGES * STAGE_BYTES;   // 110592 -> 2 CTAs/SM
    cudaFuncSetAttribute((const void*)gemm_f16_mma<true>,
                         cudaFuncAttributeMaxDynamicSharedMemorySize, SMEM_BYTES);
    cudaFuncSetAttribute((const void*)gemm_f16_mma<false>,
                         cudaFuncAttributeMaxDynamicSharedMemorySize, SMEM_BYTES);

    // Fused prep: router + x fp16 round + W1/W2 transpose (all parallel)
    prep_fused<<<PREP_TOTAL, 256>>>(x, W1, W2, view_ids, visit_ids,
                                    router_view, router_visit, loss_ptr,
                                    xh_ptr, w1t_ptr, w2t_ptr);

    // GEMM1: h = fp16(relu(x @ W1 + b1))   M=1024, N=2048, K=512
    gemm_f16_mma<true><<<dim3(DFF_ / 128, L_ / 128, B_), 256, SMEM_BYTES>>>(
        xh_ptr, w1t_ptr, b1, h_ptr, L_, DFF_, D_);

    // GEMM2: out = h @ W2 + b2             M=1024, N=512, K=2048
    gemm_f16_mma<false><<<dim3(D_ / 128, L_ / 128, B_), 256, SMEM_BYTES>>>(
        h_ptr, w2t_ptr, b2, out, L_, D_, DFF_);
}